// round 15
// baseline (speedup 1.0000x reference)
#include <cuda_runtime.h>
#include <cuda_bf16.h>
#include <cstdint>

#define T_DIM 256
#define B_DIM 256
#define H_DIM 512
#define K_DIM 64
#define M_DIM (T_DIM * B_DIM)

// Scratch (device globals; no allocations anywhere)
__device__ float g_em[(size_t)M_DIM * K_DIM];          // emissions [T,B,K] f32
__device__ unsigned long long g_Wsw[8192];             // W bf16, swizzled fragments
__device__ float g_diff[B_DIM];                        // per-batch forward - gold
__device__ unsigned int g_cnt = 0;                     // last-block counter (self-reset)
__device__ unsigned int g_flag[T_DIM];                 // per-timestep em-ready flags

__device__ __forceinline__ uint32_t f2bf2(float lo, float hi) {
    uint32_t r;
    asm("cvt.rn.bf16x2.f32 %0, %1, %2;" : "=r"(r) : "f"(hi), "f"(lo));
    return r;
}

#define CP_ASYNC16(dst32, src) \
    asm volatile("cp.async.cg.shared.global [%0], [%1], 16;" :: "r"(dst32), "l"(src))

__device__ __forceinline__ unsigned ld_acq_flag(int t) {
    unsigned v;
    asm volatile("ld.acquire.gpu.b32 %0, [%1];" : "=r"(v) : "l"(g_flag + t) : "memory");
    return v;
}
__device__ __forceinline__ void wait_flag(int t) {
    while (!ld_acq_flag(t)) __nanosleep(128);
}

// ---------------------------------------------------------------------------
// Kernel 0: prep W -> swizzled bf16 fragment layout; zero per-t flags
// ---------------------------------------------------------------------------
__global__ void prep_w(const float* __restrict__ W) {
    int i = blockIdx.x * 256 + threadIdx.x;     // 0..8191
    if (i < T_DIM) g_flag[i] = 0;
    int n  = i >> 7;
    int r  = i & 127;
    int kk = r >> 2;
    int tg = r & 3;
    float4 v = *(const float4*)(W + n * H_DIM + kk * 16 + tg * 4);
    uint32_t wl = f2bf2(v.x, v.y);
    uint32_t wh = f2bf2(v.z, v.w);
    unsigned long long u;
    asm("mov.b64 %0, {%1,%2};" : "=l"(u) : "r"(wl), "r"(wh));
    int g = n & 7, nt = n >> 3;
    int p = nt >> 1, half = nt & 1;
    g_Wsw[(kk * 4 + tg) * 64 + (p * 8 + (g ^ (tg << 1))) * 2 + half] = u;
}

// ---------------------------------------------------------------------------
// GEMM tile (R14 body as device function): em[t] slab = 256 rows x 64 cols.
// 6-stage cp.async ring (16KB stages), B fragments from L1-resident g_Wsw.
// ---------------------------------------------------------------------------
extern __shared__ char smem_raw[];

__device__ __forceinline__ void gemm_tile(int t, const float* __restrict__ hid,
                                          const float* __restrict__ bias, int tid) {
    float* sA = (float*)smem_raw;
    uint32_t sA32 = (uint32_t)__cvta_generic_to_shared(sA);
    const float* gA = hid + (size_t)t * 256 * H_DIM;

    int crow = tid >> 2;
    int cseg = tid & 3;
    uint32_t dbase0 = sA32 + cseg * 16 + crow * 64;
    const float* sbase0 = gA + (size_t)crow * H_DIM + cseg * 4;

#define ISSUE_STAGE(s) do {                                                  \
        uint32_t _d = dbase0 + ((s) % 6) * 16384;                            \
        const float* _s = sbase0 + (s) * 16;                                 \
        CP_ASYNC16(_d,          _s);                                         \
        CP_ASYNC16(_d + 4096,   _s + (size_t)64  * H_DIM);                   \
        CP_ASYNC16(_d + 8192,   _s + (size_t)128 * H_DIM);                   \
        CP_ASYNC16(_d + 12288,  _s + (size_t)192 * H_DIM);                   \
        asm volatile("cp.async.commit_group;");                              \
    } while (0)

    ISSUE_STAGE(0);
    ISSUE_STAGE(1);
    ISSUE_STAGE(2);
    ISSUE_STAGE(3);
    ISSUE_STAGE(4);

    int warp = tid >> 5;
    int lane = tid & 31;
    int g  = lane >> 2;
    int tg = lane & 3;
    int row0 = t * 256 + warp * 32;
    int afrag = warp * 512 + g * 16 + tg * 4;

    float acc[16][4];
#pragma unroll
    for (int nt = 0; nt < 16; nt++)
#pragma unroll
        for (int q = 0; q < 4; q++) acc[nt][q] = 0.f;

    for (int kk = 0; kk < 32; kk++) {
        if (kk <= 27)      { asm volatile("cp.async.wait_group 4;"); }
        else if (kk == 28) { asm volatile("cp.async.wait_group 3;"); }
        else if (kk == 29) { asm volatile("cp.async.wait_group 2;"); }
        else if (kk == 30) { asm volatile("cp.async.wait_group 1;"); }
        else               { asm volatile("cp.async.wait_group 0;"); }
        __syncthreads();
        if (kk + 5 < 32) ISSUE_STAGE(kk + 5);

        const float* abuf = sA + (kk % 6) * 4096 + afrag;
        float4 v0 = *(const float4*)(abuf);
        float4 v1 = *(const float4*)(abuf + 128);
        float4 v2 = *(const float4*)(abuf + 256);
        float4 v3 = *(const float4*)(abuf + 384);

        uint32_t a0 = f2bf2(v0.x, v0.y), a2 = f2bf2(v0.z, v0.w);
        uint32_t a1 = f2bf2(v1.x, v1.y), a3 = f2bf2(v1.z, v1.w);
        uint32_t c0 = f2bf2(v2.x, v2.y), c2 = f2bf2(v2.z, v2.w);
        uint32_t c1 = f2bf2(v3.x, v3.y), c3 = f2bf2(v3.z, v3.w);

        const unsigned long long* rowp =
            g_Wsw + ((kk * 4 + tg) << 6) + (g ^ (tg << 1)) * 2;
#pragma unroll
        for (int p = 0; p < 4; p++) {
            uint4 bb = *(const uint4*)(rowp + p * 16);
            int n0 = 2 * p, n1 = 2 * p + 1;
            asm volatile(
                "mma.sync.aligned.m16n8k16.row.col.f32.bf16.bf16.f32 "
                "{%0,%1,%2,%3}, {%4,%5,%6,%7}, {%8,%9}, {%0,%1,%2,%3};"
                : "+f"(acc[n0][0]), "+f"(acc[n0][1]), "+f"(acc[n0][2]), "+f"(acc[n0][3])
                : "r"(a0), "r"(a1), "r"(a2), "r"(a3), "r"(bb.x), "r"(bb.y));
            asm volatile(
                "mma.sync.aligned.m16n8k16.row.col.f32.bf16.bf16.f32 "
                "{%0,%1,%2,%3}, {%4,%5,%6,%7}, {%8,%9}, {%0,%1,%2,%3};"
                : "+f"(acc[n1][0]), "+f"(acc[n1][1]), "+f"(acc[n1][2]), "+f"(acc[n1][3])
                : "r"(a0), "r"(a1), "r"(a2), "r"(a3), "r"(bb.z), "r"(bb.w));
            asm volatile(
                "mma.sync.aligned.m16n8k16.row.col.f32.bf16.bf16.f32 "
                "{%0,%1,%2,%3}, {%4,%5,%6,%7}, {%8,%9}, {%0,%1,%2,%3};"
                : "+f"(acc[n0 + 8][0]), "+f"(acc[n0 + 8][1]), "+f"(acc[n0 + 8][2]), "+f"(acc[n0 + 8][3])
                : "r"(c0), "r"(c1), "r"(c2), "r"(c3), "r"(bb.x), "r"(bb.y));
            asm volatile(
                "mma.sync.aligned.m16n8k16.row.col.f32.bf16.bf16.f32 "
                "{%0,%1,%2,%3}, {%4,%5,%6,%7}, {%8,%9}, {%0,%1,%2,%3};"
                : "+f"(acc[n1 + 8][0]), "+f"(acc[n1 + 8][1]), "+f"(acc[n1 + 8][2]), "+f"(acc[n1 + 8][3])
                : "r"(c0), "r"(c1), "r"(c2), "r"(c3), "r"(bb.z), "r"(bb.w));
        }
    }
#undef ISSUE_STAGE

    int r0 = row0 + g;
#pragma unroll
    for (int nt = 0; nt < 8; nt++) {
        int c = nt * 8 + tg * 2;
        float b0v = bias[c], b1v = bias[c + 1];
        float2 o;
        o.x = acc[nt][0] + b0v; o.y = acc[nt][1] + b1v;
        *(float2*)(g_em + (size_t)r0 * K_DIM + c) = o;
        o.x = acc[nt][2] + b0v; o.y = acc[nt][3] + b1v;
        *(float2*)(g_em + (size_t)(r0 + 8) * K_DIM + c) = o;
        o.x = acc[nt + 8][0] + b0v; o.y = acc[nt + 8][1] + b1v;
        *(float2*)(g_em + (size_t)(r0 + 16) * K_DIM + c) = o;
        o.x = acc[nt + 8][2] + b0v; o.y = acc[nt + 8][3] + b1v;
        *(float2*)(g_em + (size_t)(r0 + 24) * K_DIM + c) = o;
    }
}

// ---------------------------------------------------------------------------
// Fused kernel: blocks 128..191 = producers (4 tiles each, two-ended
// schedule); blocks 0..127 = R14 bidirectional CRF DP gated on g_flag.
// ---------------------------------------------------------------------------
#define FMA2(acc, a, b) \
    asm("fma.rn.f32x2 %0, %1, %2, %3;" : "=l"(acc) : "l"(a), "l"(b), "l"(acc))

__global__ __launch_bounds__(256, 2) void fused(const float* __restrict__ hid,
                                                const float* __restrict__ bias,
                                                const int* __restrict__ lens,
                                                const int* __restrict__ tags,
                                                const float* __restrict__ trans,
                                                const float* __restrict__ begin,
                                                const float* __restrict__ endt,
                                                float* __restrict__ out) {
    int tid = threadIdx.x;

    // ================= PRODUCERS =================
    if (blockIdx.x >= 128) {
        int gb = blockIdx.x - 128;        // 0..63
#pragma unroll 1
        for (int r = 0; r < 4; r++) {
            int t = (gb < 32) ? (gb + 32 * r)
                              : (255 - ((gb - 32) + 32 * r));
            gemm_tile(t, hid, bias, tid);
            __syncthreads();
            if (tid == 0)
                asm volatile("st.release.gpu.b32 [%0], %1;"
                             :: "l"(g_flag + t), "r"(1u) : "memory");
            __syncthreads();
        }
        return;
    }

    // ================= DP (bidirectional, gated) =================
    int gid  = tid >> 6;          // 0..3
    int j    = tid & 63;
    int lane = tid & 31;
    int wing = (tid >> 5) & 1;
    int pair = gid >> 1;
    int bw   = gid & 1;
    int b    = blockIdx.x * 2 + pair;
    int len  = lens[b];
    int barid   = gid + 1;
    int pairbar = 5 + pair;

    int mid    = (len - 1) >> 1;
    int nsteps = bw ? (len - 1 - mid) : mid;

    __shared__ __align__(16) float sm_u[4][2][64];
    __shared__ __align__(16) float sm_fin[2][64];
    __shared__ float sm_g[4][2];
    __shared__ float sm_cb[2];

#define GBAR()  asm volatile("bar.sync %0, 64;"  :: "r"(barid)   : "memory")
#define PBAR()  asm volatile("bar.sync %0, 128;" :: "r"(pairbar) : "memory")
#define CT(k) ({ int _v = bw ? (len - 1 - (k)) : ((k) + 1); \
                 _v = _v < 0 ? 0 : (_v > len - 1 ? len - 1 : _v); _v; })

    // ---- exp(transition): fwd = row j of E, bwd = column j ----
    unsigned long long eT2[32];
    if (!bw) {
        const float4* tr4 = (const float4*)(trans + j * K_DIM);
#pragma unroll
        for (int q = 0; q < 16; q++) {
            float4 v = tr4[q];
            float e0 = __expf(v.x), e1 = __expf(v.y);
            float e2 = __expf(v.z), e3 = __expf(v.w);
            asm("mov.b64 %0, {%1,%2};" : "=l"(eT2[2*q])   : "f"(e0), "f"(e1));
            asm("mov.b64 %0, {%1,%2};" : "=l"(eT2[2*q+1]) : "f"(e2), "f"(e3));
        }
    } else {
#pragma unroll
        for (int q = 0; q < 32; q++) {
            float t0 = __expf(trans[(2 * q) * K_DIM + j]);
            float t1 = __expf(trans[(2 * q + 1) * K_DIM + j]);
            asm("mov.b64 %0, {%1,%2};" : "=l"(eT2[q]) : "f"(t0), "f"(t1));
        }
    }

    // ---- gate the init window: CT(0..6) plus t=0 for fwd init ----
    if (j < 7) wait_flag(CT(j));
    if (j == 7) wait_flag(bw ? CT(0) : 0);
    GBAR();

    // ---- init ----
    float u_reg, C;
    if (!bw) {
        float a00 = begin[0] + g_em[(size_t)b * K_DIM];
        u_reg = __expf(begin[j] + g_em[(size_t)b * K_DIM + j] - a00);
        C = a00;
    } else {
        float e0 = endt[0];
        u_reg = __expf(endt[j] - e0);
        C = e0;
    }

    float xq[2], e0q[2];
    float rawJ[4], raw0[4];
    {
#pragma unroll
        for (int s = 0; s < 4; s++) {
            size_t base = ((size_t)CT(s + 2) * B_DIM + b) * K_DIM;
            rawJ[s] = g_em[base + j];
            raw0[s] = g_em[base];
        }
        size_t b1 = ((size_t)CT(0) * B_DIM + b) * K_DIM;
        size_t b2 = ((size_t)CT(1) * B_DIM + b) * K_DIM;
        float e1j = g_em[b1 + j], e10 = g_em[b1];
        float e2j = g_em[b2 + j], e20 = g_em[b2];
        xq[0] = __expf(e1j - e10); e0q[0] = e10;
        xq[1] = __expf(e2j - e20); e0q[1] = e20;
    }
    sm_u[gid][0][j] = bw ? (u_reg * xq[0]) : u_reg;

    // ---- serial DP: nsteps, ONE named barrier each; gated prefetch ----
#pragma unroll 4
    for (int k = 0; k < nsteps; k++) {
        int buf = k & 1, nbuf = buf ^ 1, p = k & 3;
        GBAR();

        // early acquire of the NEXT step's prefetch flag (fast path free)
        int gk = CT(k + 7);
        unsigned fv = 1;
        if (j == 0) fv = ld_acq_flag(gk);

        const float* ubase = sm_u[gid][buf];
        float v0 = ubase[0];
        float ir;
        asm("rcp.approx.f32 %0, %1;" : "=f"(ir) : "f"(v0));

        const ulonglong2* pp = (const ulonglong2*)ubase;
        unsigned long long acc0 = 0, acc1 = 0, acc2 = 0, acc3 = 0;
#pragma unroll
        for (int q = 0; q < 16; q += 2) {
            ulonglong2 va = pp[q];
            ulonglong2 vb = pp[q + 1];
            FMA2(acc0, va.x, eT2[2*q]);
            FMA2(acc1, va.y, eT2[2*q+1]);
            FMA2(acc2, vb.x, eT2[2*q+2]);
            FMA2(acc3, vb.y, eT2[2*q+3]);
        }
        float s;
        {
            float l0, h0, l1, h1, l2, h2, l3, h3;
            asm("mov.b64 {%0,%1}, %2;" : "=f"(l0), "=f"(h0) : "l"(acc0));
            asm("mov.b64 {%0,%1}, %2;" : "=f"(l1), "=f"(h1) : "l"(acc1));
            asm("mov.b64 {%0,%1}, %2;" : "=f"(l2), "=f"(h2) : "l"(acc2));
            asm("mov.b64 {%0,%1}, %2;" : "=f"(l3), "=f"(h3) : "l"(acc3));
            s = ((l0 + h0) + (l1 + h1)) + ((l2 + h2) + (l3 + h3));
        }
        float un = bw ? (s * ir) : (s * (xq[buf] * ir));
        u_reg = un;
        C += e0q[buf] - __logf(ir);
        sm_u[gid][nbuf][j] = bw ? (un * xq[nbuf]) : un;

        float r0 = raw0[p];
        xq[buf] = __expf(rawJ[p] - r0);
        e0q[buf] = r0;
        size_t base = ((size_t)CT(k + 6) * B_DIM + b) * K_DIM;
        rawJ[p] = g_em[base + j];
        raw0[p] = g_em[base];

        if (j == 0 && fv == 0) wait_flag(gk);   // slow path: production behind
    }

    // ---- meet in the middle ----
    if (bw) {
        sm_fin[pair][j] = u_reg;
        if (j == 0) sm_cb[pair] = C;
    }
    PBAR();
    float fwd_total = 0.f;
    if (!bw) {
        float val = u_reg * sm_fin[pair][j];
#pragma unroll
        for (int o = 16; o; o >>= 1) val += __shfl_down_sync(0xffffffffu, val, o);
        if (lane == 0) sm_g[gid][wing] = val;
        GBAR();
        if (j == 0)
            fwd_total = C + sm_cb[pair] + __logf(sm_g[gid][0] + sm_g[gid][1]);
        GBAR();   // sm_g free for gold reuse

        // ---- gold path score (all t flags acquired via fwd+bwd chain+PBAR) ----
        float gpart = 0.f;
        for (int t = j; t < len; t += 64) {
            int tag = tags[t * B_DIM + b];
            float inc;
            if (t == 0) inc = begin[tag];
            else        inc = trans[tag * K_DIM + tags[(t - 1) * B_DIM + b]];
            inc += g_em[((size_t)t * B_DIM + b) * K_DIM + tag];
            gpart += inc;
        }
#pragma unroll
        for (int o = 16; o; o >>= 1) gpart += __shfl_down_sync(0xffffffffu, gpart, o);
        if (lane == 0) sm_g[gid][wing] = gpart;
        GBAR();
        if (j == 0) {
            float goldv = sm_g[gid][0] + sm_g[gid][1]
                        + endt[tags[(len - 1) * B_DIM + b]];
            g_diff[b] = fwd_total - goldv;
        }
    }
#undef GBAR
#undef PBAR
#undef CT

    // ---- fused deterministic final reduction (last DP block) ----
    __syncthreads();
    __shared__ unsigned int s_last;
    if (tid == 0) {
        __threadfence();
        unsigned int old = atomicAdd(&g_cnt, 1u);
        s_last = (old == 127u) ? 1u : 0u;
    }
    __syncthreads();
    if (s_last) {
        __shared__ float sr[256];
        if (tid == 0) __threadfence();
        __syncthreads();
        sr[tid] = __ldcg(&g_diff[tid]);
        __syncthreads();
        for (int k = 128; k > 0; k >>= 1) {
            if (tid < k) sr[tid] += sr[tid + k];
            __syncthreads();
        }
        if (tid == 0) {
            out[0] = sr[0];
            g_cnt = 0;   // reset for next graph replay
        }
    }
}

// ---------------------------------------------------------------------------
extern "C" void kernel_launch(void* const* d_in, const int* in_sizes, int n_in,
                              void* d_out, int out_size) {
    const float* hiddens = (const float*)d_in[0];   // [T,B,H] f32
    const int*   lens    = (const int*)d_in[1];     // [B]
    const int*   tags    = (const int*)d_in[2];     // [T,B]
    const float* W       = (const float*)d_in[3];   // [K,H]
    const float* bias    = (const float*)d_in[4];   // [K]
    const float* begin   = (const float*)d_in[5];   // [K]
    const float* trans   = (const float*)d_in[6];   // [K,K]
    const float* endt    = (const float*)d_in[7];   // [K]
    float* out = (float*)d_out;

    cudaFuncSetAttribute(fused, cudaFuncAttributeMaxDynamicSharedMemorySize, 98304);

    prep_w<<<32, 256>>>(W);
    fused<<<192, 256, 98304>>>(hiddens, bias, lens, tags, trans, begin, endt, out);
}

// round 16
// speedup vs baseline: 1.7934x; 1.7934x over previous
#include <cuda_runtime.h>
#include <cuda_bf16.h>
#include <cstdint>

#define T_DIM 256
#define B_DIM 256
#define H_DIM 512
#define K_DIM 64
#define M_DIM (T_DIM * B_DIM)

// Scratch (device globals; no allocations anywhere)
__device__ float g_em[(size_t)M_DIM * K_DIM];          // emissions [T,B,K] f32
__device__ unsigned long long g_Wsw[8192];             // W bf16, swizzled fragments
__device__ float g_diff[B_DIM];                        // per-batch forward - gold
__device__ unsigned int g_cnt = 0;                     // last-block counter (self-reset)
__device__ unsigned int g_flag[T_DIM];                 // per-timestep em-ready flags

__device__ __forceinline__ uint32_t f2bf2(float lo, float hi) {
    uint32_t r;
    asm("cvt.rn.bf16x2.f32 %0, %1, %2;" : "=r"(r) : "f"(hi), "f"(lo));
    return r;
}

#define CP_ASYNC16(dst32, src) \
    asm volatile("cp.async.cg.shared.global [%0], [%1], 16;" :: "r"(dst32), "l"(src))

__device__ __forceinline__ unsigned ld_acq_flag(int t) {
    unsigned v;
    asm volatile("ld.acquire.gpu.b32 %0, [%1];" : "=r"(v) : "l"(g_flag + t) : "memory");
    return v;
}
__device__ __forceinline__ void wait_flag(int t) {
    while (!ld_acq_flag(t)) __nanosleep(64);
}

// ---------------------------------------------------------------------------
// Kernel 0: prep W -> swizzled bf16 fragment layout; zero per-t flags
// ---------------------------------------------------------------------------
__global__ void prep_w(const float* __restrict__ W) {
    int i = blockIdx.x * 256 + threadIdx.x;     // 0..8191
    if (i < T_DIM) g_flag[i] = 0;
    int n  = i >> 7;
    int r  = i & 127;
    int kk = r >> 2;
    int tg = r & 3;
    float4 v = *(const float4*)(W + n * H_DIM + kk * 16 + tg * 4);
    uint32_t wl = f2bf2(v.x, v.y);
    uint32_t wh = f2bf2(v.z, v.w);
    unsigned long long u;
    asm("mov.b64 %0, {%1,%2};" : "=l"(u) : "r"(wl), "r"(wh));
    int g = n & 7, nt = n >> 3;
    int p = nt >> 1, half = nt & 1;
    g_Wsw[(kk * 4 + tg) * 64 + (p * 8 + (g ^ (tg << 1))) * 2 + half] = u;
}

// ---------------------------------------------------------------------------
// GEMM tile (R14 body): em[t] slab = 256 rows x 64 cols.
// 6-stage cp.async ring (16KB stages), B fragments from L1-resident g_Wsw.
// ---------------------------------------------------------------------------
extern __shared__ char smem_raw[];

__device__ __forceinline__ void gemm_tile(int t, const float* __restrict__ hid,
                                          const float* __restrict__ bias, int tid) {
    float* sA = (float*)smem_raw;
    uint32_t sA32 = (uint32_t)__cvta_generic_to_shared(sA);
    const float* gA = hid + (size_t)t * 256 * H_DIM;

    int crow = tid >> 2;
    int cseg = tid & 3;
    uint32_t dbase0 = sA32 + cseg * 16 + crow * 64;
    const float* sbase0 = gA + (size_t)crow * H_DIM + cseg * 4;

#define ISSUE_STAGE(s) do {                                                  \
        uint32_t _d = dbase0 + ((s) % 6) * 16384;                            \
        const float* _s = sbase0 + (s) * 16;                                 \
        CP_ASYNC16(_d,          _s);                                         \
        CP_ASYNC16(_d + 4096,   _s + (size_t)64  * H_DIM);                   \
        CP_ASYNC16(_d + 8192,   _s + (size_t)128 * H_DIM);                   \
        CP_ASYNC16(_d + 12288,  _s + (size_t)192 * H_DIM);                   \
        asm volatile("cp.async.commit_group;");                              \
    } while (0)

    ISSUE_STAGE(0);
    ISSUE_STAGE(1);
    ISSUE_STAGE(2);
    ISSUE_STAGE(3);
    ISSUE_STAGE(4);

    int warp = tid >> 5;
    int lane = tid & 31;
    int g  = lane >> 2;
    int tg = lane & 3;
    int row0 = t * 256 + warp * 32;
    int afrag = warp * 512 + g * 16 + tg * 4;

    float acc[16][4];
#pragma unroll
    for (int nt = 0; nt < 16; nt++)
#pragma unroll
        for (int q = 0; q < 4; q++) acc[nt][q] = 0.f;

    for (int kk = 0; kk < 32; kk++) {
        if (kk <= 27)      { asm volatile("cp.async.wait_group 4;"); }
        else if (kk == 28) { asm volatile("cp.async.wait_group 3;"); }
        else if (kk == 29) { asm volatile("cp.async.wait_group 2;"); }
        else if (kk == 30) { asm volatile("cp.async.wait_group 1;"); }
        else               { asm volatile("cp.async.wait_group 0;"); }
        __syncthreads();
        if (kk + 5 < 32) ISSUE_STAGE(kk + 5);

        const float* abuf = sA + (kk % 6) * 4096 + afrag;
        float4 v0 = *(const float4*)(abuf);
        float4 v1 = *(const float4*)(abuf + 128);
        float4 v2 = *(const float4*)(abuf + 256);
        float4 v3 = *(const float4*)(abuf + 384);

        uint32_t a0 = f2bf2(v0.x, v0.y), a2 = f2bf2(v0.z, v0.w);
        uint32_t a1 = f2bf2(v1.x, v1.y), a3 = f2bf2(v1.z, v1.w);
        uint32_t c0 = f2bf2(v2.x, v2.y), c2 = f2bf2(v2.z, v2.w);
        uint32_t c1 = f2bf2(v3.x, v3.y), c3 = f2bf2(v3.z, v3.w);

        const unsigned long long* rowp =
            g_Wsw + ((kk * 4 + tg) << 6) + (g ^ (tg << 1)) * 2;
#pragma unroll
        for (int p = 0; p < 4; p++) {
            uint4 bb = *(const uint4*)(rowp + p * 16);
            int n0 = 2 * p, n1 = 2 * p + 1;
            asm volatile(
                "mma.sync.aligned.m16n8k16.row.col.f32.bf16.bf16.f32 "
                "{%0,%1,%2,%3}, {%4,%5,%6,%7}, {%8,%9}, {%0,%1,%2,%3};"
                : "+f"(acc[n0][0]), "+f"(acc[n0][1]), "+f"(acc[n0][2]), "+f"(acc[n0][3])
                : "r"(a0), "r"(a1), "r"(a2), "r"(a3), "r"(bb.x), "r"(bb.y));
            asm volatile(
                "mma.sync.aligned.m16n8k16.row.col.f32.bf16.bf16.f32 "
                "{%0,%1,%2,%3}, {%4,%5,%6,%7}, {%8,%9}, {%0,%1,%2,%3};"
                : "+f"(acc[n1][0]), "+f"(acc[n1][1]), "+f"(acc[n1][2]), "+f"(acc[n1][3])
                : "r"(a0), "r"(a1), "r"(a2), "r"(a3), "r"(bb.z), "r"(bb.w));
            asm volatile(
                "mma.sync.aligned.m16n8k16.row.col.f32.bf16.bf16.f32 "
                "{%0,%1,%2,%3}, {%4,%5,%6,%7}, {%8,%9}, {%0,%1,%2,%3};"
                : "+f"(acc[n0 + 8][0]), "+f"(acc[n0 + 8][1]), "+f"(acc[n0 + 8][2]), "+f"(acc[n0 + 8][3])
                : "r"(c0), "r"(c1), "r"(c2), "r"(c3), "r"(bb.x), "r"(bb.y));
            asm volatile(
                "mma.sync.aligned.m16n8k16.row.col.f32.bf16.bf16.f32 "
                "{%0,%1,%2,%3}, {%4,%5,%6,%7}, {%8,%9}, {%0,%1,%2,%3};"
                : "+f"(acc[n1 + 8][0]), "+f"(acc[n1 + 8][1]), "+f"(acc[n1 + 8][2]), "+f"(acc[n1 + 8][3])
                : "r"(c0), "r"(c1), "r"(c2), "r"(c3), "r"(bb.z), "r"(bb.w));
        }
    }
#undef ISSUE_STAGE

    int r0 = row0 + g;
#pragma unroll
    for (int nt = 0; nt < 8; nt++) {
        int c = nt * 8 + tg * 2;
        float b0v = bias[c], b1v = bias[c + 1];
        float2 o;
        o.x = acc[nt][0] + b0v; o.y = acc[nt][1] + b1v;
        *(float2*)(g_em + (size_t)r0 * K_DIM + c) = o;
        o.x = acc[nt][2] + b0v; o.y = acc[nt][3] + b1v;
        *(float2*)(g_em + (size_t)(r0 + 8) * K_DIM + c) = o;
        o.x = acc[nt + 8][0] + b0v; o.y = acc[nt + 8][1] + b1v;
        *(float2*)(g_em + (size_t)(r0 + 16) * K_DIM + c) = o;
        o.x = acc[nt + 8][2] + b0v; o.y = acc[nt + 8][3] + b1v;
        *(float2*)(g_em + (size_t)(r0 + 24) * K_DIM + c) = o;
    }
}

// ---------------------------------------------------------------------------
// Fused kernel, grid 256 (all co-resident at 2/SM): EVERY block produces
// em[t=blockIdx.x] at full GEMM bandwidth, sets its flag, then blocks
// 0..127 fall through into the gated bidirectional DP (proven R15 logic).
// ---------------------------------------------------------------------------
#define FMA2(acc, a, b) \
    asm("fma.rn.f32x2 %0, %1, %2, %3;" : "=l"(acc) : "l"(a), "l"(b), "l"(acc))

__global__ __launch_bounds__(256, 2) void fused(const float* __restrict__ hid,
                                                const float* __restrict__ bias,
                                                const int* __restrict__ lens,
                                                const int* __restrict__ tags,
                                                const float* __restrict__ trans,
                                                const float* __restrict__ begin,
                                                const float* __restrict__ endt,
                                                float* __restrict__ out) {
    int tid = threadIdx.x;

    // ---- phase 1: every block produces its own timestep tile ----
    gemm_tile(blockIdx.x, hid, bias, tid);
    __syncthreads();
    if (tid == 0) {
        __threadfence();
        asm volatile("st.release.gpu.b32 [%0], %1;"
                     :: "l"(g_flag + blockIdx.x), "r"(1u) : "memory");
    }
    if (blockIdx.x >= 128) return;

    // ---- phase 2: DP (bidirectional, gated) on blocks 0..127 ----
    int gid  = tid >> 6;          // 0..3
    int j    = tid & 63;
    int lane = tid & 31;
    int wing = (tid >> 5) & 1;
    int pair = gid >> 1;
    int bw   = gid & 1;
    int b    = blockIdx.x * 2 + pair;
    int len  = lens[b];
    int barid   = gid + 1;
    int pairbar = 5 + pair;

    int mid    = (len - 1) >> 1;
    int nsteps = bw ? (len - 1 - mid) : mid;

    __shared__ __align__(16) float sm_u[4][2][64];
    __shared__ __align__(16) float sm_fin[2][64];
    __shared__ float sm_g[4][2];
    __shared__ float sm_cb[2];

#define GBAR()  asm volatile("bar.sync %0, 64;"  :: "r"(barid)   : "memory")
#define PBAR()  asm volatile("bar.sync %0, 128;" :: "r"(pairbar) : "memory")
#define CT(k) ({ int _v = bw ? (len - 1 - (k)) : ((k) + 1); \
                 _v = _v < 0 ? 0 : (_v > len - 1 ? len - 1 : _v); _v; })

    // ---- exp(transition): fwd = row j of E, bwd = column j ----
    unsigned long long eT2[32];
    if (!bw) {
        const float4* tr4 = (const float4*)(trans + j * K_DIM);
#pragma unroll
        for (int q = 0; q < 16; q++) {
            float4 v = tr4[q];
            float e0 = __expf(v.x), e1 = __expf(v.y);
            float e2 = __expf(v.z), e3 = __expf(v.w);
            asm("mov.b64 %0, {%1,%2};" : "=l"(eT2[2*q])   : "f"(e0), "f"(e1));
            asm("mov.b64 %0, {%1,%2};" : "=l"(eT2[2*q+1]) : "f"(e2), "f"(e3));
        }
    } else {
#pragma unroll
        for (int q = 0; q < 32; q++) {
            float t0 = __expf(trans[(2 * q) * K_DIM + j]);
            float t1 = __expf(trans[(2 * q + 1) * K_DIM + j]);
            asm("mov.b64 %0, {%1,%2};" : "=l"(eT2[q]) : "f"(t0), "f"(t1));
        }
    }

    // ---- gate the init window: CT(0..6) plus t=0 for fwd init ----
    if (j < 7) wait_flag(CT(j));
    if (j == 7) wait_flag(bw ? CT(0) : 0);
    GBAR();

    // ---- init ----
    float u_reg, C;
    if (!bw) {
        float a00 = begin[0] + g_em[(size_t)b * K_DIM];
        u_reg = __expf(begin[j] + g_em[(size_t)b * K_DIM + j] - a00);
        C = a00;
    } else {
        float e0 = endt[0];
        u_reg = __expf(endt[j] - e0);
        C = e0;
    }

    float xq[2], e0q[2];
    float rawJ[4], raw0[4];
    {
#pragma unroll
        for (int s = 0; s < 4; s++) {
            size_t base = ((size_t)CT(s + 2) * B_DIM + b) * K_DIM;
            rawJ[s] = g_em[base + j];
            raw0[s] = g_em[base];
        }
        size_t b1 = ((size_t)CT(0) * B_DIM + b) * K_DIM;
        size_t b2 = ((size_t)CT(1) * B_DIM + b) * K_DIM;
        float e1j = g_em[b1 + j], e10 = g_em[b1];
        float e2j = g_em[b2 + j], e20 = g_em[b2];
        xq[0] = __expf(e1j - e10); e0q[0] = e10;
        xq[1] = __expf(e2j - e20); e0q[1] = e20;
    }
    sm_u[gid][0][j] = bw ? (u_reg * xq[0]) : u_reg;

    // ---- serial DP: nsteps, ONE named barrier each; gated prefetch ----
#pragma unroll 4
    for (int k = 0; k < nsteps; k++) {
        int buf = k & 1, nbuf = buf ^ 1, p = k & 3;
        GBAR();

        int gk = CT(k + 7);
        unsigned fv = 1;
        if (j == 0) fv = ld_acq_flag(gk);

        const float* ubase = sm_u[gid][buf];
        float v0 = ubase[0];
        float ir;
        asm("rcp.approx.f32 %0, %1;" : "=f"(ir) : "f"(v0));

        const ulonglong2* pp = (const ulonglong2*)ubase;
        unsigned long long acc0 = 0, acc1 = 0, acc2 = 0, acc3 = 0;
#pragma unroll
        for (int q = 0; q < 16; q += 2) {
            ulonglong2 va = pp[q];
            ulonglong2 vb = pp[q + 1];
            FMA2(acc0, va.x, eT2[2*q]);
            FMA2(acc1, va.y, eT2[2*q+1]);
            FMA2(acc2, vb.x, eT2[2*q+2]);
            FMA2(acc3, vb.y, eT2[2*q+3]);
        }
        float s;
        {
            float l0, h0, l1, h1, l2, h2, l3, h3;
            asm("mov.b64 {%0,%1}, %2;" : "=f"(l0), "=f"(h0) : "l"(acc0));
            asm("mov.b64 {%0,%1}, %2;" : "=f"(l1), "=f"(h1) : "l"(acc1));
            asm("mov.b64 {%0,%1}, %2;" : "=f"(l2), "=f"(h2) : "l"(acc2));
            asm("mov.b64 {%0,%1}, %2;" : "=f"(l3), "=f"(h3) : "l"(acc3));
            s = ((l0 + h0) + (l1 + h1)) + ((l2 + h2) + (l3 + h3));
        }
        float un = bw ? (s * ir) : (s * (xq[buf] * ir));
        u_reg = un;
        C += e0q[buf] - __logf(ir);
        sm_u[gid][nbuf][j] = bw ? (un * xq[nbuf]) : un;

        float r0 = raw0[p];
        xq[buf] = __expf(rawJ[p] - r0);
        e0q[buf] = r0;
        size_t base = ((size_t)CT(k + 6) * B_DIM + b) * K_DIM;
        rawJ[p] = g_em[base + j];
        raw0[p] = g_em[base];

        if (j == 0 && fv == 0) wait_flag(gk);
    }

    // ---- meet in the middle ----
    if (bw) {
        sm_fin[pair][j] = u_reg;
        if (j == 0) sm_cb[pair] = C;
    }
    PBAR();
    float fwd_total = 0.f;
    if (!bw) {
        float val = u_reg * sm_fin[pair][j];
#pragma unroll
        for (int o = 16; o; o >>= 1) val += __shfl_down_sync(0xffffffffu, val, o);
        if (lane == 0) sm_g[gid][wing] = val;
        GBAR();
        if (j == 0)
            fwd_total = C + sm_cb[pair] + __logf(sm_g[gid][0] + sm_g[gid][1]);
        GBAR();

        // ---- gold path score (all needed flags acquired by DP chain) ----
        float gpart = 0.f;
        for (int t = j; t < len; t += 64) {
            int tag = tags[t * B_DIM + b];
            float inc;
            if (t == 0) inc = begin[tag];
            else        inc = trans[tag * K_DIM + tags[(t - 1) * B_DIM + b]];
            inc += g_em[((size_t)t * B_DIM + b) * K_DIM + tag];
            gpart += inc;
        }
#pragma unroll
        for (int o = 16; o; o >>= 1) gpart += __shfl_down_sync(0xffffffffu, gpart, o);
        if (lane == 0) sm_g[gid][wing] = gpart;
        GBAR();
        if (j == 0) {
            float goldv = sm_g[gid][0] + sm_g[gid][1]
                        + endt[tags[(len - 1) * B_DIM + b]];
            g_diff[b] = fwd_total - goldv;
        }
    }
#undef GBAR
#undef PBAR
#undef CT

    // ---- fused deterministic final reduction (last DP block) ----
    __syncthreads();
    __shared__ unsigned int s_last;
    if (tid == 0) {
        __threadfence();
        unsigned int old = atomicAdd(&g_cnt, 1u);
        s_last = (old == 127u) ? 1u : 0u;
    }
    __syncthreads();
    if (s_last) {
        __shared__ float sr[256];
        if (tid == 0) __threadfence();
        __syncthreads();
        sr[tid] = __ldcg(&g_diff[tid]);
        __syncthreads();
        for (int k = 128; k > 0; k >>= 1) {
            if (tid < k) sr[tid] += sr[tid + k];
            __syncthreads();
        }
        if (tid == 0) {
            out[0] = sr[0];
            g_cnt = 0;   // reset for next graph replay
        }
    }
}

// ---------------------------------------------------------------------------
extern "C" void kernel_launch(void* const* d_in, const int* in_sizes, int n_in,
                              void* d_out, int out_size) {
    const float* hiddens = (const float*)d_in[0];   // [T,B,H] f32
    const int*   lens    = (const int*)d_in[1];     // [B]
    const int*   tags    = (const int*)d_in[2];     // [T,B]
    const float* W       = (const float*)d_in[3];   // [K,H]
    const float* bias    = (const float*)d_in[4];   // [K]
    const float* begin   = (const float*)d_in[5];   // [K]
    const float* trans   = (const float*)d_in[6];   // [K,K]
    const float* endt    = (const float*)d_in[7];   // [K]
    float* out = (float*)d_out;

    cudaFuncSetAttribute(fused, cudaFuncAttributeMaxDynamicSharedMemorySize, 98304);

    prep_w<<<32, 256>>>(W);
    fused<<<256, 256, 98304>>>(hiddens, bias, lens, tags, trans, begin, endt, out);
}

// round 17
// speedup vs baseline: 2.1602x; 1.2045x over previous
#include <cuda_runtime.h>
#include <cuda_bf16.h>
#include <cstdint>

#define T_DIM 256
#define B_DIM 256
#define H_DIM 512
#define K_DIM 64
#define M_DIM (T_DIM * B_DIM)

// Scratch (device globals; no allocations anywhere)
__device__ float g_em[(size_t)M_DIM * K_DIM];          // emissions [T,B,K] f32
__device__ unsigned long long g_Wsw[8192];             // W bf16, swizzled fragments
__device__ float g_diff[B_DIM];                        // per-batch forward - gold
__device__ unsigned int g_cnt = 0;                     // last-block counter (self-reset)
__device__ unsigned int g_wflag = 0;                   // W-ready flag (self-reset)

__device__ __forceinline__ uint32_t f2bf2(float lo, float hi) {
    uint32_t r;
    asm("cvt.rn.bf16x2.f32 %0, %1, %2;" : "=r"(r) : "f"(hi), "f"(lo));
    return r;
}

#define CP_ASYNC16(dst32, src) \
    asm volatile("cp.async.cg.shared.global [%0], [%1], 16;" :: "r"(dst32), "l"(src))

// ---------------------------------------------------------------------------
// Kernel 1: emissions GEMM (R14 body) with W-prep folded in.
// All blocks: issue 5 A-prefetch stages first (no W dependency). Block 0:
// convert+swizzle W into g_Wsw (hidden under A prefetch), release g_wflag.
// Others: one spin-acquire. 6-stage cp.async ring; B from L1-resident g_Wsw.
// ---------------------------------------------------------------------------
extern __shared__ char smem_raw[];

__global__ __launch_bounds__(256, 2) void emis_gemm(const float* __restrict__ hid,
                                                    const float* __restrict__ W,
                                                    const float* __restrict__ bias) {
    int tid = threadIdx.x;
    float* sA = (float*)smem_raw;
    uint32_t sA32 = (uint32_t)__cvta_generic_to_shared(sA);
    const float* gA = hid + (size_t)blockIdx.x * 256 * H_DIM;

    int crow = tid >> 2;
    int cseg = tid & 3;
    uint32_t dbase0 = sA32 + cseg * 16 + crow * 64;
    const float* sbase0 = gA + (size_t)crow * H_DIM + cseg * 4;

#define ISSUE_STAGE(s) do {                                                  \
        uint32_t _d = dbase0 + ((s) % 6) * 16384;                            \
        const float* _s = sbase0 + (s) * 16;                                 \
        CP_ASYNC16(_d,          _s);                                         \
        CP_ASYNC16(_d + 4096,   _s + (size_t)64  * H_DIM);                   \
        CP_ASYNC16(_d + 8192,   _s + (size_t)128 * H_DIM);                   \
        CP_ASYNC16(_d + 12288,  _s + (size_t)192 * H_DIM);                   \
        asm volatile("cp.async.commit_group;");                              \
    } while (0)

    ISSUE_STAGE(0);
    ISSUE_STAGE(1);
    ISSUE_STAGE(2);
    ISSUE_STAGE(3);
    ISSUE_STAGE(4);

    // ---- W prep (block 0) / acquire (others), overlapped with A prefetch ----
    if (blockIdx.x == 0) {
        for (int i = tid; i < 8192; i += 256) {
            int n  = i >> 7;
            int r  = i & 127;
            int kk = r >> 2;
            int tg = r & 3;
            float4 v = *(const float4*)(W + n * H_DIM + kk * 16 + tg * 4);
            uint32_t wl = f2bf2(v.x, v.y);
            uint32_t wh = f2bf2(v.z, v.w);
            unsigned long long u;
            asm("mov.b64 %0, {%1,%2};" : "=l"(u) : "r"(wl), "r"(wh));
            int g = n & 7, nt = n >> 3;
            int p = nt >> 1, half = nt & 1;
            g_Wsw[(kk * 4 + tg) * 64 + (p * 8 + (g ^ (tg << 1))) * 2 + half] = u;
        }
        __syncthreads();
        if (tid == 0) {
            __threadfence();
            asm volatile("st.release.gpu.b32 [%0], %1;"
                         :: "l"(&g_wflag), "r"(1u) : "memory");
        }
    } else if (tid == 0) {
        unsigned v;
        do {
            asm volatile("ld.acquire.gpu.b32 %0, [%1];"
                         : "=r"(v) : "l"(&g_wflag) : "memory");
            if (!v) __nanosleep(64);
        } while (!v);
    }
    __syncthreads();   // W visible to the whole block

    int warp = tid >> 5;
    int lane = tid & 31;
    int g  = lane >> 2;
    int tg = lane & 3;
    int row0 = blockIdx.x * 256 + warp * 32;
    int afrag = warp * 512 + g * 16 + tg * 4;

    float acc[16][4];
#pragma unroll
    for (int nt = 0; nt < 16; nt++)
#pragma unroll
        for (int q = 0; q < 4; q++) acc[nt][q] = 0.f;

    for (int kk = 0; kk < 32; kk++) {
        if (kk <= 27)      { asm volatile("cp.async.wait_group 4;"); }
        else if (kk == 28) { asm volatile("cp.async.wait_group 3;"); }
        else if (kk == 29) { asm volatile("cp.async.wait_group 2;"); }
        else if (kk == 30) { asm volatile("cp.async.wait_group 1;"); }
        else               { asm volatile("cp.async.wait_group 0;"); }
        __syncthreads();
        if (kk + 5 < 32) ISSUE_STAGE(kk + 5);

        const float* abuf = sA + (kk % 6) * 4096 + afrag;
        float4 v0 = *(const float4*)(abuf);          // row g
        float4 v1 = *(const float4*)(abuf + 128);    // row g+8
        float4 v2 = *(const float4*)(abuf + 256);    // row g+16
        float4 v3 = *(const float4*)(abuf + 384);    // row g+24

        uint32_t a0 = f2bf2(v0.x, v0.y), a2 = f2bf2(v0.z, v0.w);
        uint32_t a1 = f2bf2(v1.x, v1.y), a3 = f2bf2(v1.z, v1.w);
        uint32_t c0 = f2bf2(v2.x, v2.y), c2 = f2bf2(v2.z, v2.w);
        uint32_t c1 = f2bf2(v3.x, v3.y), c3 = f2bf2(v3.z, v3.w);

        const unsigned long long* rowp =
            g_Wsw + ((kk * 4 + tg) << 6) + (g ^ (tg << 1)) * 2;
#pragma unroll
        for (int p = 0; p < 4; p++) {
            uint4 bb = *(const uint4*)(rowp + p * 16);
            int n0 = 2 * p, n1 = 2 * p + 1;
            asm volatile(
                "mma.sync.aligned.m16n8k16.row.col.f32.bf16.bf16.f32 "
                "{%0,%1,%2,%3}, {%4,%5,%6,%7}, {%8,%9}, {%0,%1,%2,%3};"
                : "+f"(acc[n0][0]), "+f"(acc[n0][1]), "+f"(acc[n0][2]), "+f"(acc[n0][3])
                : "r"(a0), "r"(a1), "r"(a2), "r"(a3), "r"(bb.x), "r"(bb.y));
            asm volatile(
                "mma.sync.aligned.m16n8k16.row.col.f32.bf16.bf16.f32 "
                "{%0,%1,%2,%3}, {%4,%5,%6,%7}, {%8,%9}, {%0,%1,%2,%3};"
                : "+f"(acc[n1][0]), "+f"(acc[n1][1]), "+f"(acc[n1][2]), "+f"(acc[n1][3])
                : "r"(a0), "r"(a1), "r"(a2), "r"(a3), "r"(bb.z), "r"(bb.w));
            asm volatile(
                "mma.sync.aligned.m16n8k16.row.col.f32.bf16.bf16.f32 "
                "{%0,%1,%2,%3}, {%4,%5,%6,%7}, {%8,%9}, {%0,%1,%2,%3};"
                : "+f"(acc[n0 + 8][0]), "+f"(acc[n0 + 8][1]), "+f"(acc[n0 + 8][2]), "+f"(acc[n0 + 8][3])
                : "r"(c0), "r"(c1), "r"(c2), "r"(c3), "r"(bb.x), "r"(bb.y));
            asm volatile(
                "mma.sync.aligned.m16n8k16.row.col.f32.bf16.bf16.f32 "
                "{%0,%1,%2,%3}, {%4,%5,%6,%7}, {%8,%9}, {%0,%1,%2,%3};"
                : "+f"(acc[n1 + 8][0]), "+f"(acc[n1 + 8][1]), "+f"(acc[n1 + 8][2]), "+f"(acc[n1 + 8][3])
                : "r"(c0), "r"(c1), "r"(c2), "r"(c3), "r"(bb.z), "r"(bb.w));
        }
    }
#undef ISSUE_STAGE

    int r0 = row0 + g;
#pragma unroll
    for (int nt = 0; nt < 8; nt++) {
        int c = nt * 8 + tg * 2;
        float b0v = bias[c], b1v = bias[c + 1];
        float2 o;
        o.x = acc[nt][0] + b0v; o.y = acc[nt][1] + b1v;
        *(float2*)(g_em + (size_t)r0 * K_DIM + c) = o;
        o.x = acc[nt][2] + b0v; o.y = acc[nt][3] + b1v;
        *(float2*)(g_em + (size_t)(r0 + 8) * K_DIM + c) = o;
        o.x = acc[nt + 8][0] + b0v; o.y = acc[nt + 8][1] + b1v;
        *(float2*)(g_em + (size_t)(r0 + 16) * K_DIM + c) = o;
        o.x = acc[nt + 8][2] + b0v; o.y = acc[nt + 8][3] + b1v;
        *(float2*)(g_em + (size_t)(r0 + 24) * K_DIM + c) = o;
    }
}

// ---------------------------------------------------------------------------
// Kernel 2: BIDIRECTIONAL CRF DP + gold + fused final reduction.
// (R14 measured-best; last block also resets g_wflag for graph replay)
// ---------------------------------------------------------------------------
#define FMA2(acc, a, b) \
    asm("fma.rn.f32x2 %0, %1, %2, %3;" : "=l"(acc) : "l"(a), "l"(b), "l"(acc))

__global__ __launch_bounds__(256) void crf_dp(const int* __restrict__ lens,
                                              const int* __restrict__ tags,
                                              const float* __restrict__ trans,
                                              const float* __restrict__ begin,
                                              const float* __restrict__ endt,
                                              float* __restrict__ out) {
    int tid  = threadIdx.x;
    int gid  = tid >> 6;
    int j    = tid & 63;
    int lane = tid & 31;
    int wing = (tid >> 5) & 1;
    int pair = gid >> 1;
    int bw   = gid & 1;
    int b    = blockIdx.x * 2 + pair;
    int len  = lens[b];
    int barid   = gid + 1;
    int pairbar = 5 + pair;

    int mid    = (len - 1) >> 1;
    int nsteps = bw ? (len - 1 - mid) : mid;

    __shared__ __align__(16) float sm_u[4][2][64];
    __shared__ __align__(16) float sm_fin[2][64];
    __shared__ float sm_g[4][2];
    __shared__ float sm_cb[2];

#define GBAR()  asm volatile("bar.sync %0, 64;"  :: "r"(barid)   : "memory")
#define PBAR()  asm volatile("bar.sync %0, 128;" :: "r"(pairbar) : "memory")

    float goldv = 0.f;
    if (!bw) {
        float gpart = 0.f;
        for (int t = j; t < len; t += 64) {
            int tag = tags[t * B_DIM + b];
            float inc;
            if (t == 0) inc = begin[tag];
            else        inc = trans[tag * K_DIM + tags[(t - 1) * B_DIM + b]];
            inc += g_em[((size_t)t * B_DIM + b) * K_DIM + tag];
            gpart += inc;
        }
#pragma unroll
        for (int o = 16; o; o >>= 1) gpart += __shfl_down_sync(0xffffffffu, gpart, o);
        if (lane == 0) sm_g[gid][wing] = gpart;
        GBAR();
        if (j == 0)
            goldv = sm_g[gid][0] + sm_g[gid][1] + endt[tags[(len - 1) * B_DIM + b]];
    }

    unsigned long long eT2[32];
    if (!bw) {
        const float4* tr4 = (const float4*)(trans + j * K_DIM);
#pragma unroll
        for (int q = 0; q < 16; q++) {
            float4 v = tr4[q];
            float e0 = __expf(v.x), e1 = __expf(v.y);
            float e2 = __expf(v.z), e3 = __expf(v.w);
            asm("mov.b64 %0, {%1,%2};" : "=l"(eT2[2*q])   : "f"(e0), "f"(e1));
            asm("mov.b64 %0, {%1,%2};" : "=l"(eT2[2*q+1]) : "f"(e2), "f"(e3));
        }
    } else {
#pragma unroll
        for (int q = 0; q < 32; q++) {
            float t0 = __expf(trans[(2 * q) * K_DIM + j]);
            float t1 = __expf(trans[(2 * q + 1) * K_DIM + j]);
            asm("mov.b64 %0, {%1,%2};" : "=l"(eT2[q]) : "f"(t0), "f"(t1));
        }
    }

#define CT(k) ({ int _v = bw ? (len - 1 - (k)) : ((k) + 1); \
                 _v = _v < 0 ? 0 : (_v > len - 1 ? len - 1 : _v); _v; })

    float u_reg, C;
    if (!bw) {
        float a00 = begin[0] + g_em[(size_t)b * K_DIM];
        u_reg = __expf(begin[j] + g_em[(size_t)b * K_DIM + j] - a00);
        C = a00;
    } else {
        float e0 = endt[0];
        u_reg = __expf(endt[j] - e0);
        C = e0;
    }

    float xq[2], e0q[2];
    float rawJ[4], raw0[4];
    {
#pragma unroll
        for (int s = 0; s < 4; s++) {
            size_t base = ((size_t)CT(s + 2) * B_DIM + b) * K_DIM;
            rawJ[s] = g_em[base + j];
            raw0[s] = g_em[base];
        }
        size_t b1 = ((size_t)CT(0) * B_DIM + b) * K_DIM;
        size_t b2 = ((size_t)CT(1) * B_DIM + b) * K_DIM;
        float e1j = g_em[b1 + j], e10 = g_em[b1];
        float e2j = g_em[b2 + j], e20 = g_em[b2];
        xq[0] = __expf(e1j - e10); e0q[0] = e10;
        xq[1] = __expf(e2j - e20); e0q[1] = e20;
    }
    sm_u[gid][0][j] = bw ? (u_reg * xq[0]) : u_reg;

#pragma unroll 4
    for (int k = 0; k < nsteps; k++) {
        int buf = k & 1, nbuf = buf ^ 1, p = k & 3;
        GBAR();

        const float* ubase = sm_u[gid][buf];
        float v0 = ubase[0];
        float ir;
        asm("rcp.approx.f32 %0, %1;" : "=f"(ir) : "f"(v0));

        const ulonglong2* pp = (const ulonglong2*)ubase;
        unsigned long long acc0 = 0, acc1 = 0, acc2 = 0, acc3 = 0;
#pragma unroll
        for (int q = 0; q < 16; q += 2) {
            ulonglong2 va = pp[q];
            ulonglong2 vb = pp[q + 1];
            FMA2(acc0, va.x, eT2[2*q]);
            FMA2(acc1, va.y, eT2[2*q+1]);
            FMA2(acc2, vb.x, eT2[2*q+2]);
            FMA2(acc3, vb.y, eT2[2*q+3]);
        }
        float s;
        {
            float l0, h0, l1, h1, l2, h2, l3, h3;
            asm("mov.b64 {%0,%1}, %2;" : "=f"(l0), "=f"(h0) : "l"(acc0));
            asm("mov.b64 {%0,%1}, %2;" : "=f"(l1), "=f"(h1) : "l"(acc1));
            asm("mov.b64 {%0,%1}, %2;" : "=f"(l2), "=f"(h2) : "l"(acc2));
            asm("mov.b64 {%0,%1}, %2;" : "=f"(l3), "=f"(h3) : "l"(acc3));
            s = ((l0 + h0) + (l1 + h1)) + ((l2 + h2) + (l3 + h3));
        }
        float un = bw ? (s * ir) : (s * (xq[buf] * ir));
        u_reg = un;
        C += e0q[buf] - __logf(ir);
        sm_u[gid][nbuf][j] = bw ? (un * xq[nbuf]) : un;

        float r0 = raw0[p];
        xq[buf] = __expf(rawJ[p] - r0);
        e0q[buf] = r0;
        size_t base = ((size_t)CT(k + 6) * B_DIM + b) * K_DIM;
        rawJ[p] = g_em[base + j];
        raw0[p] = g_em[base];
    }
#undef CT

    if (bw) {
        sm_fin[pair][j] = u_reg;
        if (j == 0) sm_cb[pair] = C;
    }
    PBAR();
    if (!bw) {
        float val = u_reg * sm_fin[pair][j];
#pragma unroll
        for (int o = 16; o; o >>= 1) val += __shfl_down_sync(0xffffffffu, val, o);
        if (lane == 0) sm_g[gid][wing] = val;
        GBAR();
        if (j == 0) {
            float fwd = C + sm_cb[pair] + __logf(sm_g[gid][0] + sm_g[gid][1]);
            g_diff[b] = fwd - goldv;
        }
    }
#undef GBAR
#undef PBAR

    __syncthreads();
    __shared__ unsigned int s_last;
    if (tid == 0) {
        __threadfence();
        unsigned int old = atomicAdd(&g_cnt, 1u);
        s_last = (old == (unsigned)(gridDim.x - 1)) ? 1u : 0u;
    }
    __syncthreads();
    if (s_last) {
        __shared__ float sr[256];
        if (tid == 0) __threadfence();
        __syncthreads();
        sr[tid] = __ldcg(&g_diff[tid]);
        __syncthreads();
        for (int k = 128; k > 0; k >>= 1) {
            if (tid < k) sr[tid] += sr[tid + k];
            __syncthreads();
        }
        if (tid == 0) {
            out[0] = sr[0];
            g_cnt = 0;     // reset for next graph replay
            g_wflag = 0;   // reset W-ready flag for next graph replay
        }
    }
}

// ---------------------------------------------------------------------------
extern "C" void kernel_launch(void* const* d_in, const int* in_sizes, int n_in,
                              void* d_out, int out_size) {
    const float* hiddens = (const float*)d_in[0];   // [T,B,H] f32
    const int*   lens    = (const int*)d_in[1];     // [B]
    const int*   tags    = (const int*)d_in[2];     // [T,B]
    const float* W       = (const float*)d_in[3];   // [K,H]
    const float* bias    = (const float*)d_in[4];   // [K]
    const float* begin   = (const float*)d_in[5];   // [K]
    const float* trans   = (const float*)d_in[6];   // [K,K]
    const float* endt    = (const float*)d_in[7];   // [K]
    float* out = (float*)d_out;

    cudaFuncSetAttribute(emis_gemm, cudaFuncAttributeMaxDynamicSharedMemorySize, 98304);

    emis_gemm<<<M_DIM / 256, 256, 98304>>>(hiddens, W, bias);
    crf_dp<<<B_DIM / 2, 256>>>(lens, tags, trans, begin, endt, out);
}